// round 1
// baseline (speedup 1.0000x reference)
#include <cuda_runtime.h>
#include <cstdint>

#define BB 256   // batch
#define DD 256   // groups
#define KK 1024  // codes
#define EE 16    // embed dim
#define DECAY 0.999f
#define GAINF 0.001f
#define EPSF 1e-6f

#define ACC_STRIDE 17  // pad to kill smem bank conflicts on scatter atomics

// smem layout (floats):
//   cb_s  [KK*EE]          = 16384
//   c2_s  [KK]             =  1024
//   acc_s [KK*ACC_STRIDE]  = 17408
//   cnt_s [KK]             =  1024
//   idx_s [BB] (as int)    =   256
// total = 36096 floats = 144384 bytes
#define SMEM_FLOATS (KK*EE + KK + KK*ACC_STRIDE + KK + BB)

__global__ __launch_bounds__(256, 1)
void vqvae_fused_kernel(const float* __restrict__ cw_q,      // [B, D*E]
                        const float* __restrict__ codebook,  // [D, K, E]
                        const float* __restrict__ ema,       // [D, K]
                        float* __restrict__ out_embed,       // [B, D*E]
                        float* __restrict__ out_onehot,      // [B, D, K]
                        float* __restrict__ out_cb,          // [D, K, E]
                        float* __restrict__ out_ema)         // [D, K]
{
    const int d   = blockIdx.x;
    const int tid = threadIdx.x;

    extern __shared__ float sm[];
    float* cb_s  = sm;                       // KK*EE
    float* c2_s  = cb_s  + KK*EE;            // KK
    float* acc_s = c2_s  + KK;               // KK*ACC_STRIDE
    float* cnt_s = acc_s + KK*ACC_STRIDE;    // KK
    int*   idx_s = (int*)(cnt_s + KK);       // BB

    // ---- Phase 0: load codebook[d] slice (64 KB) coalesced; zero accumulators ----
    {
        const float4* cbg = (const float4*)(codebook + (size_t)d * KK * EE);
        float4* cb4 = (float4*)cb_s;
        #pragma unroll
        for (int i = tid; i < KK*EE/4; i += 256)
            cb4[i] = cbg[i];
        for (int i = tid; i < KK*ACC_STRIDE; i += 256)
            acc_s[i] = 0.0f;
        for (int k = tid; k < KK; k += 256)
            cnt_s[k] = 0.0f;
    }
    __syncthreads();

    // ---- Phase 1: c2[k] = ||codebook[d,k]||^2 ----
    for (int k = tid; k < KK; k += 256) {
        float s = 0.0f;
        #pragma unroll
        for (int e = 0; e < EE; e++) {
            float v = cb_s[k*EE + e];
            s = fmaf(v, v, s);
        }
        c2_s[k] = s;
    }
    __syncthreads();

    // ---- Phase 2: per-thread b-row argmin over K codes ----
    const int b = tid;  // 256 threads == 256 batch rows
    float x[EE];
    {
        const float4* xg = (const float4*)(cw_q + (size_t)b * (DD*EE) + (size_t)d * EE);
        #pragma unroll
        for (int i = 0; i < EE/4; i++) {
            float4 v = xg[i];
            x[i*4+0] = v.x; x[i*4+1] = v.y; x[i*4+2] = v.z; x[i*4+3] = v.w;
        }
    }
    float x2 = 0.0f;
    #pragma unroll
    for (int e = 0; e < EE; e++) x2 = fmaf(x[e], x[e], x2);

    float best = __int_as_float(0x7f800000);  // +inf
    int   bi   = 0;
    #pragma unroll 2
    for (int k = 0; k < KK; k++) {
        const float* c = cb_s + k*EE;
        float dot = 0.0f;
        #pragma unroll
        for (int e = 0; e < EE; e++)
            dot = fmaf(x[e], c[e], dot);
        float dist = (x2 + c2_s[k]) - 2.0f * dot;
        if (dist < best) { best = dist; bi = k; }
    }
    idx_s[b] = bi;

    // cw_embed[b, d*E .. ] = codebook[d, bi, :]
    {
        float4* eo = (float4*)(out_embed + (size_t)b * (DD*EE) + (size_t)d * EE);
        const float4* src = (const float4*)(cb_s + bi*EE);
        #pragma unroll
        for (int i = 0; i < EE/4; i++) eo[i] = src[i];
    }

    // scatter-accumulate update & counts in smem (padded stride -> spread banks)
    #pragma unroll
    for (int e = 0; e < EE; e++)
        atomicAdd(&acc_s[bi*ACC_STRIDE + e], x[e]);
    atomicAdd(&cnt_s[bi], 1.0f);
    __syncthreads();

    // ---- Phase 3: cooperative, fully-coalesced one_hot writes ----
    // one_hot[bb, d, :] : 1024 floats, each thread stores one float4 (k = tid*4..tid*4+3)
    {
        const int kb = tid * 4;
        for (int bb = 0; bb < BB; bb++) {
            int ki = idx_s[bb];
            float4 v = make_float4(0.f, 0.f, 0.f, 0.f);
            if (ki >= kb && ki < kb + 4)
                ((float*)&v)[ki - kb] = 1.0f;
            *(float4*)(out_onehot + (size_t)bb * (DD*KK) + (size_t)d * KK + kb) = v;
        }
    }

    // ---- Phase 4: epilogue — new_codebook & new_ema ----
    {
        const float* emag = ema    + (size_t)d * KK;
        float* ocb        = out_cb + (size_t)d * KK * EE;
        float* oem        = out_ema+ (size_t)d * KK;
        for (int k = tid; k < KK; k += 256) {
            float em  = emag[k];
            float den = 1.0f / (em + EPSF);
            float4 o[EE/4];
            #pragma unroll
            for (int e = 0; e < EE; e++)
                ((float*)o)[e] = cb_s[k*EE + e] * DECAY
                               + GAINF * acc_s[k*ACC_STRIDE + e] * den;
            float4* dst = (float4*)(ocb + (size_t)k * EE);
            #pragma unroll
            for (int i = 0; i < EE/4; i++) dst[i] = o[i];
            oem[k] = DECAY * em + GAINF * cnt_s[k];
        }
    }
}

extern "C" void kernel_launch(void* const* d_in, const int* in_sizes, int n_in,
                              void* d_out, int out_size)
{
    const float* cw_q     = (const float*)d_in[0];
    const float* codebook = (const float*)d_in[1];
    const float* ema      = (const float*)d_in[2];

    float* out        = (float*)d_out;
    float* out_embed  = out;                                   // B*D*E   = 1,048,576
    float* out_onehot = out_embed  + (size_t)BB * DD * EE;     // B*D*K   = 67,108,864
    float* out_cb     = out_onehot + (size_t)BB * DD * KK;     // D*K*E   = 4,194,304
    float* out_ema    = out_cb     + (size_t)DD * KK * EE;     // D*K     = 262,144

    const size_t smem_bytes = (size_t)SMEM_FLOATS * sizeof(float);
    // >48KB dynamic smem needs an opt-in; idempotent host call, not stream-captured.
    cudaFuncSetAttribute(vqvae_fused_kernel,
                         cudaFuncAttributeMaxDynamicSharedMemorySize,
                         (int)smem_bytes);

    vqvae_fused_kernel<<<DD, 256, smem_bytes>>>(
        cw_q, codebook, ema, out_embed, out_onehot, out_cb, out_ema);
}

// round 2
// speedup vs baseline: 1.0889x; 1.0889x over previous
#include <cuda_runtime.h>
#include <cstdint>

#define BB 256   // batch
#define DD 256   // groups
#define KK 1024  // codes
#define EE 16    // embed dim
#define DECAY 0.999f
#define GAINF 0.001f
#define EPSF 1e-6f

#define ACC_STRIDE 17   // pad scatter-atomic rows across banks
#define NT 1024         // threads per block
#define NQ 4            // K-quarters
#define KPQ (KK / NQ)   // 256 codes per quarter

typedef unsigned long long u64;

// packed fp32x2 FMA (sm_103a): d = a*b + c on two lanes
__device__ __forceinline__ u64 fma2(u64 a, u64 b, u64 c) {
    u64 d;
    asm("fma.rn.f32x2 %0, %1, %2, %3;" : "=l"(d) : "l"(a), "l"(b), "l"(c));
    return d;
}
__device__ __forceinline__ float2 upk(u64 v) {
    float2 r;
    asm("mov.b64 {%0, %1}, %2;" : "=f"(r.x), "=f"(r.y) : "l"(v));
    return r;
}

// smem layout (floats):
//   cb_s  [KK*EE]         16384
//   c2_s  [KK]             1024
//   acc_s [KK*ACC_STRIDE] 17408
//   cnt_s [KK]             1024
//   red_d [NQ*BB]          1024
//   red_i [NQ*BB] (int)    1024
#define SMEM_FLOATS (KK*EE + KK + KK*ACC_STRIDE + KK + NQ*BB + NQ*BB)

__global__ __launch_bounds__(NT, 1)
void vqvae_fused_kernel(const float* __restrict__ cw_q,      // [B, D*E]
                        const float* __restrict__ codebook,  // [D, K, E]
                        const float* __restrict__ ema,       // [D, K]
                        float* __restrict__ out_embed,       // [B, D*E]
                        float* __restrict__ out_onehot,      // [B, D, K]
                        float* __restrict__ out_cb,          // [D, K, E]
                        float* __restrict__ out_ema)         // [D, K]
{
    const int d   = blockIdx.x;
    const int tid = threadIdx.x;

    extern __shared__ float sm[];
    float* cb_s  = sm;                        // 16384
    float* c2_s  = cb_s  + KK*EE;             // 1024
    float* acc_s = c2_s  + KK;                // 17408
    float* cnt_s = acc_s + KK*ACC_STRIDE;     // 1024
    float* red_d = cnt_s + KK;                // 1024
    int*   red_i = (int*)(red_d + NQ*BB);     // 1024

    // ---- Phase 0: codebook slice -> smem; zero accumulators; zero one_hot ----
    {
        const float4* cbg = (const float4*)(codebook + (size_t)d * KK * EE);
        float4* cb4 = (float4*)cb_s;
        #pragma unroll
        for (int i = tid; i < KK*EE/4; i += NT)
            cb4[i] = cbg[i];
        for (int i = tid; i < KK*ACC_STRIDE; i += NT)
            acc_s[i] = 0.0f;
        cnt_s[tid & (KK-1)] = 0.0f;   // NT == KK

        // dependency-free one_hot zero-fill: overlaps the compute phase's DRAM drain
        const float4 z = make_float4(0.f, 0.f, 0.f, 0.f);
        const int kb = tid & 255;                 // float4 column
        for (int bb = tid >> 8; bb < BB; bb += NQ)
            ((float4*)(out_onehot + (size_t)bb * (DD*KK) + (size_t)d * KK))[kb] = z;
    }
    __syncthreads();

    // ---- Phase 1: c2[k] = ||codebook[d,k]||^2  (one k per thread) ----
    {
        const int k = tid;
        const float4* row = (const float4*)(cb_s + k*EE);
        float s = 0.0f;
        #pragma unroll
        for (int i = 0; i < EE/4; i++) {
            float4 v = row[i];
            s = fmaf(v.x, v.x, s); s = fmaf(v.y, v.y, s);
            s = fmaf(v.z, v.z, s); s = fmaf(v.w, v.w, s);
        }
        c2_s[k] = s;
    }
    __syncthreads();

    // ---- Phase 2: argmin; thread (b = tid&255, q = tid>>8) scans quarter q ----
    const int b = tid & 255;
    const int q = tid >> 8;

    u64 xp[8];
    {
        const ulonglong2* xg =
            (const ulonglong2*)(cw_q + (size_t)b * (DD*EE) + (size_t)d * EE);
        #pragma unroll
        for (int i = 0; i < 4; i++) {
            ulonglong2 v = xg[i];
            xp[2*i]   = v.x;
            xp[2*i+1] = v.y;
        }
    }
    float x2 = 0.0f;
    #pragma unroll
    for (int i = 0; i < 8; i++) {
        float2 v = upk(xp[i]);
        x2 = fmaf(v.x, v.x, x2);
        x2 = fmaf(v.y, v.y, x2);
    }

    const int k0 = q * KPQ;
    float best = __int_as_float(0x7f800000);  // +inf
    int   bi   = k0;
    const ulonglong2* cbp = (const ulonglong2*)cb_s;
    #pragma unroll 2
    for (int k = k0; k < k0 + KPQ; k++) {
        ulonglong2 p0 = cbp[k*4+0];
        ulonglong2 p1 = cbp[k*4+1];
        ulonglong2 p2 = cbp[k*4+2];
        ulonglong2 p3 = cbp[k*4+3];
        u64 a0 = fma2(xp[0], p0.x, 0ull);
        u64 a1 = fma2(xp[2], p1.x, 0ull);
        a0 = fma2(xp[1], p0.y, a0);
        a1 = fma2(xp[3], p1.y, a1);
        a0 = fma2(xp[4], p2.x, a0);
        a1 = fma2(xp[5], p2.y, a1);
        a0 = fma2(xp[6], p3.x, a0);
        a1 = fma2(xp[7], p3.y, a1);
        float2 s0 = upk(a0), s1 = upk(a1);
        float dot  = (s0.x + s1.x) + (s0.y + s1.y);
        float dist = fmaf(-2.0f, dot, x2 + c2_s[k]);
        if (dist < best) { best = dist; bi = k; }
    }
    red_d[tid] = best;
    red_i[tid] = bi;
    __syncthreads();

    // ---- Phase 3: final argmin across quarters; embed, one_hot '1', scatter ----
    if (tid < BB) {
        float fb = red_d[tid];
        int   fi = red_i[tid];
        #pragma unroll
        for (int qq = 1; qq < NQ; qq++) {          // ascending k => first-min ties
            float dq = red_d[qq*BB + tid];
            if (dq < fb) { fb = dq; fi = red_i[qq*BB + tid]; }
        }
        // cw_embed[b] = codebook[d, fi, :]
        {
            const float4* src = (const float4*)(cb_s + fi*EE);
            float4* eo = (float4*)(out_embed + (size_t)tid * (DD*EE) + (size_t)d * EE);
            #pragma unroll
            for (int i = 0; i < EE/4; i++) eo[i] = src[i];
        }
        // one_hot '1' (ordered after the zero-fill by the __syncthreads above)
        out_onehot[(size_t)tid * (DD*KK) + (size_t)d * KK + fi] = 1.0f;

        // scatter-accumulate x into code fi (this thread's xp IS row b=tid, q=0)
        #pragma unroll
        for (int i = 0; i < 8; i++) {
            float2 v = upk(xp[i]);
            atomicAdd(&acc_s[fi*ACC_STRIDE + 2*i],     v.x);
            atomicAdd(&acc_s[fi*ACC_STRIDE + 2*i + 1], v.y);
        }
        atomicAdd(&cnt_s[fi], 1.0f);
    }
    __syncthreads();

    // ---- Phase 4: epilogue (one k per thread) ----
    {
        const int k = tid;
        const float em  = ema[(size_t)d * KK + k];
        const float den = GAINF / (em + EPSF);
        float4 o[EE/4];
        #pragma unroll
        for (int e = 0; e < EE; e++)
            ((float*)o)[e] = cb_s[k*EE + e] * DECAY + acc_s[k*ACC_STRIDE + e] * den;
        float4* dst = (float4*)(out_cb + (size_t)d * KK * EE + (size_t)k * EE);
        #pragma unroll
        for (int i = 0; i < EE/4; i++) dst[i] = o[i];
        out_ema[(size_t)d * KK + k] = DECAY * em + GAINF * cnt_s[k];
    }
}

extern "C" void kernel_launch(void* const* d_in, const int* in_sizes, int n_in,
                              void* d_out, int out_size)
{
    const float* cw_q     = (const float*)d_in[0];
    const float* codebook = (const float*)d_in[1];
    const float* ema      = (const float*)d_in[2];

    float* out        = (float*)d_out;
    float* out_embed  = out;                                   // B*D*E
    float* out_onehot = out_embed  + (size_t)BB * DD * EE;     // B*D*K
    float* out_cb     = out_onehot + (size_t)BB * DD * KK;     // D*K*E
    float* out_ema    = out_cb     + (size_t)DD * KK * EE;     // D*K

    const size_t smem_bytes = (size_t)SMEM_FLOATS * sizeof(float);
    cudaFuncSetAttribute(vqvae_fused_kernel,
                         cudaFuncAttributeMaxDynamicSharedMemorySize,
                         (int)smem_bytes);

    vqvae_fused_kernel<<<DD, NT, smem_bytes>>>(
        cw_q, codebook, ema, out_embed, out_onehot, out_cb, out_ema);
}

// round 3
// speedup vs baseline: 1.1771x; 1.0810x over previous
#include <cuda_runtime.h>
#include <cstdint>

#define BB 256   // batch
#define DD 256   // groups
#define KK 1024  // codes
#define EE 16    // embed dim
#define DECAY 0.999f
#define GAINF 0.001f
#define EPSF 1e-6f

#define NT 256          // threads per block
#define NQ 4            // K-splits
#define KPQ (KK / NQ)   // 256 codes per split
#define BPT 4           // batch rows per thread

typedef unsigned long long u64;

__device__ __forceinline__ u64 fma2(u64 a, u64 b, u64 c) {
    u64 d; asm("fma.rn.f32x2 %0, %1, %2, %3;" : "=l"(d) : "l"(a), "l"(b), "l"(c));
    return d;
}
__device__ __forceinline__ u64 add2(u64 a, u64 b) {
    u64 d; asm("add.rn.f32x2 %0, %1, %2;" : "=l"(d) : "l"(a), "l"(b));
    return d;
}
__device__ __forceinline__ float2 upk(u64 v) {
    float2 r; asm("mov.b64 {%0, %1}, %2;" : "=f"(r.x), "=f"(r.y) : "l"(v));
    return r;
}

// smem (floats): cb 16384 | c2 1024 | x 4096 | den 1024 | red_d 1024 | red_i 1024
//              = 24576 floats = 96 KB  -> 2 CTAs/SM (192 KB <= 228 KB)
#define SMEM_FLOATS (KK*EE + KK + BB*EE + KK + NQ*BB + NQ*BB)

__global__ __launch_bounds__(NT, 2)
void vqvae_fused_kernel(const float* __restrict__ cw_q,      // [B, D*E]
                        const float* __restrict__ codebook,  // [D, K, E]
                        const float* __restrict__ ema,       // [D, K]
                        float* __restrict__ out_embed,       // [B, D*E]
                        float* __restrict__ out_onehot,      // [B, D, K]
                        float* __restrict__ out_cb,          // [D, K, E]
                        float* __restrict__ out_ema)         // [D, K]
{
    const int d   = blockIdx.x;
    const int tid = threadIdx.x;

    extern __shared__ float sm[];
    float* cb_s  = sm;                     // KK*EE
    float* c2_s  = cb_s  + KK*EE;          // KK
    float* x_s   = c2_s  + KK;             // BB*EE
    float* den_s = x_s   + BB*EE;          // KK  : GAIN/(ema+eps)
    float* red_d = den_s + KK;             // NQ*BB
    int*   red_i = (int*)(red_d + NQ*BB);  // NQ*BB

    // ---- Phase 0a: codebook -> smem, and write out_cb base = DECAY*cb ----
    {
        const float4* cbg = (const float4*)(codebook + (size_t)d * KK * EE);
        float4*       ob4 = (float4*)(out_cb   + (size_t)d * KK * EE);
        float4*       cb4 = (float4*)cb_s;
        #pragma unroll
        for (int i = tid; i < KK*EE/4; i += NT) {
            float4 v = cbg[i];
            cb4[i] = v;
            float4 w = make_float4(v.x*DECAY, v.y*DECAY, v.z*DECAY, v.w*DECAY);
            ob4[i] = w;
        }
    }
    // ---- Phase 0b: ema -> out_ema base (DECAY*ema), den_s = GAIN/(ema+eps) ----
    {
        const float* eg = ema + (size_t)d * KK;
        float*       oe = out_ema + (size_t)d * KK;
        #pragma unroll
        for (int k = tid; k < KK; k += NT) {
            float em = eg[k];
            oe[k]    = DECAY * em;
            den_s[k] = GAINF / (em + EPSF);
        }
    }
    // ---- Phase 0c: x rows -> smem ----
    {
        const int b    = tid;  // NT == BB
        const float4* xg = (const float4*)(cw_q + (size_t)b * (DD*EE) + (size_t)d * EE);
        float4* xs = (float4*)(x_s + b*EE);
        #pragma unroll
        for (int i = 0; i < EE/4; i++) xs[i] = xg[i];
    }
    // ---- Phase 0d: dependency-free one_hot zero-fill (drains under compute) ----
    {
        const float4 z = make_float4(0.f, 0.f, 0.f, 0.f);
        float4* base = (float4*)(out_onehot + (size_t)d * KK) + tid;  // column tid
        #pragma unroll 4
        for (int bb = 0; bb < BB; bb++)
            base[(size_t)bb * (DD*KK/4)] = z;
    }
    __syncthreads();

    // ---- Phase 1: c2[k] = ||codebook[d,k]||^2 ----
    #pragma unroll
    for (int k = tid; k < KK; k += NT) {
        const float4* row = (const float4*)(cb_s + k*EE);
        float s = 0.0f;
        #pragma unroll
        for (int i = 0; i < EE/4; i++) {
            float4 v = row[i];
            s = fmaf(v.x, v.x, s); s = fmaf(v.y, v.y, s);
            s = fmaf(v.z, v.z, s); s = fmaf(v.w, v.w, s);
        }
        c2_s[k] = s;
    }
    __syncthreads();

    // ---- Phase 2: argmin. thread (bg = tid&63, q = tid>>6) scans KPQ codes
    //      for 4 batch rows b = bg*4 .. bg*4+3 ----
    const int bg = tid & 63;
    const int q  = tid >> 6;
    const int k0 = q * KPQ;

    u64 xp[BPT][EE/2];
    {
        const ulonglong2* xr = (const ulonglong2*)(x_s + bg*BPT*EE);
        #pragma unroll
        for (int j = 0; j < BPT; j++)
            #pragma unroll
            for (int i = 0; i < 4; i++) {
                ulonglong2 v = xr[j*4 + i];
                xp[j][2*i]   = v.x;
                xp[j][2*i+1] = v.y;
            }
    }

    float best[BPT];
    int   bi[BPT];
    #pragma unroll
    for (int j = 0; j < BPT; j++) { best[j] = __int_as_float(0x7f800000); bi[j] = k0; }

    const ulonglong2* cbp = (const ulonglong2*)cb_s;
    #pragma unroll 1
    for (int k = k0; k < k0 + KPQ; k++) {
        ulonglong2 p0 = cbp[k*4+0];
        ulonglong2 p1 = cbp[k*4+1];
        ulonglong2 p2 = cbp[k*4+2];
        ulonglong2 p3 = cbp[k*4+3];
        float c2k = c2_s[k];
        #pragma unroll
        for (int j = 0; j < BPT; j++) {
            u64 a0 = fma2(xp[j][0], p0.x, 0ull);
            u64 a1 = fma2(xp[j][4], p2.x, 0ull);
            a0 = fma2(xp[j][1], p0.y, a0);
            a1 = fma2(xp[j][5], p2.y, a1);
            a0 = fma2(xp[j][2], p1.x, a0);
            a1 = fma2(xp[j][6], p3.x, a1);
            a0 = fma2(xp[j][3], p1.y, a0);
            a1 = fma2(xp[j][7], p3.y, a1);
            float2 s = upk(add2(a0, a1));
            float dist = fmaf(-2.0f, s.x + s.y, c2k);
            if (dist < best[j]) { best[j] = dist; bi[j] = k; }
        }
    }
    #pragma unroll
    for (int j = 0; j < BPT; j++) {
        red_d[q*BB + bg*BPT + j] = best[j];
        red_i[q*BB + bg*BPT + j] = bi[j];
    }
    __syncthreads();

    // ---- Phase 3: final argmin across splits; embed, one_hot '1', EMA updates ----
    {
        const int b = tid;  // NT == BB
        float fb = red_d[b];
        int   fi = red_i[b];
        #pragma unroll
        for (int qq = 1; qq < NQ; qq++) {     // ascending k => first-index ties
            float dq = red_d[qq*BB + b];
            if (dq < fb) { fb = dq; fi = red_i[qq*BB + b]; }
        }

        // cw_embed[b] = codebook[d, fi, :]
        {
            const float4* src = (const float4*)(cb_s + fi*EE);
            float4* eo = (float4*)(out_embed + (size_t)b * (DD*EE) + (size_t)d * EE);
            #pragma unroll
            for (int i = 0; i < EE/4; i++) eo[i] = src[i];
        }
        // one_hot '1' (ordered after this block's zero-fill by __syncthreads)
        out_onehot[(size_t)b * (DD*KK) + (size_t)d * KK + fi] = 1.0f;

        // new_codebook += den[fi] * x[b]   (base DECAY*cb written in phase 0a,
        // ordered by the __syncthreads above; out_cb[d] owned by this block)
        const float den = den_s[fi];
        float* dst = out_cb + (size_t)d * KK * EE + (size_t)fi * EE;
        const float* xb = x_s + b*EE;
        #pragma unroll
        for (int e = 0; e < EE; e++)
            atomicAdd(&dst[e], den * xb[e]);

        // new_ema += GAIN per selection
        atomicAdd(&out_ema[(size_t)d * KK + fi], GAINF);
    }
}

extern "C" void kernel_launch(void* const* d_in, const int* in_sizes, int n_in,
                              void* d_out, int out_size)
{
    const float* cw_q     = (const float*)d_in[0];
    const float* codebook = (const float*)d_in[1];
    const float* ema      = (const float*)d_in[2];

    float* out        = (float*)d_out;
    float* out_embed  = out;                                   // B*D*E
    float* out_onehot = out_embed  + (size_t)BB * DD * EE;     // B*D*K
    float* out_cb     = out_onehot + (size_t)BB * DD * KK;     // D*K*E
    float* out_ema    = out_cb     + (size_t)DD * KK * EE;     // D*K

    const size_t smem_bytes = (size_t)SMEM_FLOATS * sizeof(float);
    cudaFuncSetAttribute(vqvae_fused_kernel,
                         cudaFuncAttributeMaxDynamicSharedMemorySize,
                         (int)smem_bytes);

    vqvae_fused_kernel<<<DD, NT, smem_bytes>>>(
        cw_q, codebook, ema, out_embed, out_onehot, out_cb, out_ema);
}

// round 4
// speedup vs baseline: 1.2564x; 1.0674x over previous
#include <cuda_runtime.h>
#include <cstdint>

#define BB 256   // batch
#define DD 256   // groups
#define KK 1024  // codes
#define EE 16    // embed dim
#define DECAY 0.999f
#define GAINF 0.001f
#define EPSF 1e-6f

#define NS  2           // K halves, one block each
#define KH  (KK / NS)   // 512 codes per block
#define NT1 256
#define NQ  2           // in-block K splits
#define KPT (KH / NQ)   // 256 codes per thread
#define BPT 2           // batch rows per thread

typedef unsigned long long u64;

__device__ __forceinline__ u64 fma2(u64 a, u64 b, u64 c) {
    u64 d; asm("fma.rn.f32x2 %0, %1, %2, %3;" : "=l"(d) : "l"(a), "l"(b), "l"(c));
    return d;
}
__device__ __forceinline__ u64 add2(u64 a, u64 b) {
    u64 d; asm("add.rn.f32x2 %0, %1, %2;" : "=l"(d) : "l"(a), "l"(b));
    return d;
}
__device__ __forceinline__ float2 upk(u64 v) {
    float2 r; asm("mov.b64 {%0, %1}, %2;" : "=f"(r.x), "=f"(r.y) : "l"(v));
    return r;
}

// partial results: packed (dist_bits<<32 | global_k) per (d, b, half)
__device__ u64 g_scratch[(size_t)DD * BB * NS];

// k1 smem (floats): cb 8192 | c2h 512 | red_d 512 | red_i 512 | zbuf 1024 = 10752 (42 KB)
#define SM1_FLOATS (KH*EE + KH + NQ*BB + NQ*BB + KK)

__global__ __launch_bounds__(NT1, 3)
void vq_k1(const float* __restrict__ cw_q,      // [B, D*E]
           const float* __restrict__ codebook,  // [D, K, E]
           const float* __restrict__ ema,       // [D, K]
           float* __restrict__ out_onehot,      // [B, D, K]
           float* __restrict__ out_cb,          // [D, K, E]
           float* __restrict__ out_ema)         // [D, K]
{
    const int d   = blockIdx.x >> 1;
    const int h   = blockIdx.x & 1;
    const int tid = threadIdx.x;

    extern __shared__ float sm[];
    float* cb_s  = sm;                      // KH*EE
    float* c2_s  = cb_s + KH*EE;            // KH   (0.5*||c||^2)
    float* red_d = c2_s + KH;               // NQ*BB
    int*   red_i = (int*)(red_d + NQ*BB);   // NQ*BB
    float* zbuf  = (float*)(red_i + NQ*BB); // KK zeros (one one_hot row)

    // ---- Phase 0: codebook half -> smem; out_cb decay base; zbuf; ema base ----
    {
        const float4* cbg = (const float4*)(codebook + (size_t)d * KK * EE
                                                     + (size_t)h * KH * EE);
        float4* ob4 = (float4*)(out_cb + (size_t)d * KK * EE + (size_t)h * KH * EE);
        float4* cb4 = (float4*)cb_s;
        #pragma unroll
        for (int i = tid; i < KH*EE/4; i += NT1) {
            float4 v = cbg[i];
            cb4[i] = v;
            ob4[i] = make_float4(v.x*DECAY, v.y*DECAY, v.z*DECAY, v.w*DECAY);
        }
        for (int i = tid; i < KK; i += NT1) zbuf[i] = 0.0f;
        if (h == 0) {
            const float* eg = ema + (size_t)d * KK;
            float*       oe = out_ema + (size_t)d * KK;
            for (int k = tid; k < KK; k += NT1) oe[k] = DECAY * eg[k];
        }
    }
    __syncthreads();
    // generic->async proxy ordering before TMA reads zbuf
    asm volatile("fence.proxy.async.shared::cta;" ::: "memory");

    // ---- one_hot zero rows via bulk async store (TMA pipe, off the LSU) ----
    if (tid < BB/NS) {
        const int bb = h * (BB/NS) + tid;
        float* grow = out_onehot + (size_t)bb * (DD*KK) + (size_t)d * KK;
        uint32_t zs = (uint32_t)__cvta_generic_to_shared(zbuf);
        asm volatile("cp.async.bulk.global.shared::cta.bulk_group [%0], [%1], %2;"
                     :: "l"(grow), "r"(zs), "r"(KK*4) : "memory");
        asm volatile("cp.async.bulk.commit_group;" ::: "memory");
    }

    // ---- Phase 1: c2h[k] = 0.5*||c_k||^2 ----
    #pragma unroll
    for (int k = tid; k < KH; k += NT1) {
        const float4* row = (const float4*)(cb_s + k*EE);
        float s = 0.0f;
        #pragma unroll
        for (int i = 0; i < EE/4; i++) {
            float4 v = row[i];
            s = fmaf(v.x, v.x, s); s = fmaf(v.y, v.y, s);
            s = fmaf(v.z, v.z, s); s = fmaf(v.w, v.w, s);
        }
        c2_s[k] = 0.5f * s;
    }
    __syncthreads();

    // ---- Phase 2: argmin over this half. thread (bg = tid&127, q = tid>>7) ----
    const int bg = tid & 127;
    const int q  = tid >> 7;
    const int b0 = bg * BPT;
    const int k0 = q * KPT;

    u64 xp[BPT][EE/2];
    #pragma unroll
    for (int j = 0; j < BPT; j++) {
        const ulonglong2* xg = (const ulonglong2*)(cw_q
                              + (size_t)(b0 + j) * (DD*EE) + (size_t)d * EE);
        #pragma unroll
        for (int i = 0; i < 4; i++) {
            ulonglong2 v = xg[i];
            xp[j][2*i]   = v.x;
            xp[j][2*i+1] = v.y;
        }
    }

    float best[BPT];
    int   bi[BPT];
    #pragma unroll
    for (int j = 0; j < BPT; j++) { best[j] = __int_as_float(0x7f800000); bi[j] = k0; }

    const ulonglong2* cbp = (const ulonglong2*)cb_s;
    #pragma unroll 2
    for (int k = k0; k < k0 + KPT; k++) {
        ulonglong2 p0 = cbp[k*4+0];
        ulonglong2 p1 = cbp[k*4+1];
        ulonglong2 p2 = cbp[k*4+2];
        ulonglong2 p3 = cbp[k*4+3];
        float c2k = c2_s[k];
        #pragma unroll
        for (int j = 0; j < BPT; j++) {
            u64 a0 = fma2(xp[j][0], p0.x, 0ull);
            u64 a1 = fma2(xp[j][4], p2.x, 0ull);
            a0 = fma2(xp[j][1], p0.y, a0);
            a1 = fma2(xp[j][5], p2.y, a1);
            a0 = fma2(xp[j][2], p1.x, a0);
            a1 = fma2(xp[j][6], p3.x, a1);
            a0 = fma2(xp[j][3], p1.y, a0);
            a1 = fma2(xp[j][7], p3.y, a1);
            float2 s = upk(add2(a0, a1));
            float dist = c2k - (s.x + s.y);     // x^2 dropped: argmin-invariant
            if (dist < best[j]) { best[j] = dist; bi[j] = k; }
        }
    }
    #pragma unroll
    for (int j = 0; j < BPT; j++) {
        red_d[q*BB + b0 + j] = best[j];
        red_i[q*BB + b0 + j] = bi[j];
    }
    __syncthreads();

    // ---- combine q-splits (ascending q => first-min ties), write scratch ----
    {
        const int b = tid;  // NT1 == BB
        float fb = red_d[b];
        int   fi = red_i[b];
        float d1 = red_d[BB + b];
        if (d1 < fb) { fb = d1; fi = red_i[BB + b]; }
        g_scratch[((size_t)d * BB + b) * NS + h] =
            ((u64)(uint32_t)__float_as_uint(fb) << 32) | (uint32_t)(fi + h*KH);
    }

    if (tid < BB/NS)
        asm volatile("cp.async.bulk.wait_group 0;" ::: "memory");
}

// ---- kernel 2: per-d final combine + epilogue ----
#define SM2_FLOATS (KK*EE)   // 64 KB codebook slice

__global__ __launch_bounds__(256)
void vq_k2(const float* __restrict__ cw_q,
           const float* __restrict__ codebook,
           const float* __restrict__ ema,
           float* __restrict__ out_embed,
           float* __restrict__ out_onehot,
           float* __restrict__ out_cb,
           float* __restrict__ out_ema)
{
    const int d = blockIdx.x;
    const int b = threadIdx.x;

    extern __shared__ float cb_s[];
    {
        const float4* cbg = (const float4*)(codebook + (size_t)d * KK * EE);
        float4* cb4 = (float4*)cb_s;
        #pragma unroll
        for (int i = b; i < KK*EE/4; i += 256) cb4[i] = cbg[i];
    }

    u64 p0 = g_scratch[((size_t)d * BB + b) * NS + 0];
    u64 p1 = g_scratch[((size_t)d * BB + b) * NS + 1];
    float f0 = __uint_as_float((uint32_t)(p0 >> 32));
    float f1 = __uint_as_float((uint32_t)(p1 >> 32));
    int   fi = (f1 < f0) ? (int)(uint32_t)(p1 & 0xffffffffu)
                         : (int)(uint32_t)(p0 & 0xffffffffu);
    __syncthreads();

    // cw_embed[b, d] = codebook[d, fi]
    {
        const float4* src = (const float4*)(cb_s + fi*EE);
        float4* eo = (float4*)(out_embed + (size_t)b * (DD*EE) + (size_t)d * EE);
        #pragma unroll
        for (int i = 0; i < EE/4; i++) eo[i] = src[i];
    }
    // one_hot '1' (zeros written by k1, ordered by kernel boundary)
    out_onehot[(size_t)b * (DD*KK) + (size_t)d * KK + fi] = 1.0f;

    // EMA updates (bases written by k1)
    const float em  = ema[(size_t)d * KK + fi];
    const float den = GAINF / (em + EPSF);
    const float* xb = cw_q + (size_t)b * (DD*EE) + (size_t)d * EE;
    float* dst = out_cb + (size_t)d * KK * EE + (size_t)fi * EE;
    #pragma unroll
    for (int e = 0; e < EE; e++)
        atomicAdd(&dst[e], den * xb[e]);
    atomicAdd(&out_ema[(size_t)d * KK + fi], GAINF);
}

extern "C" void kernel_launch(void* const* d_in, const int* in_sizes, int n_in,
                              void* d_out, int out_size)
{
    const float* cw_q     = (const float*)d_in[0];
    const float* codebook = (const float*)d_in[1];
    const float* ema      = (const float*)d_in[2];

    float* out        = (float*)d_out;
    float* out_embed  = out;                                   // B*D*E
    float* out_onehot = out_embed  + (size_t)BB * DD * EE;     // B*D*K
    float* out_cb     = out_onehot + (size_t)BB * DD * KK;     // D*K*E
    float* out_ema    = out_cb     + (size_t)DD * KK * EE;     // D*K

    const size_t sm1 = (size_t)SM1_FLOATS * sizeof(float);
    const size_t sm2 = (size_t)SM2_FLOATS * sizeof(float);
    cudaFuncSetAttribute(vq_k1, cudaFuncAttributeMaxDynamicSharedMemorySize, (int)sm1);
    cudaFuncSetAttribute(vq_k2, cudaFuncAttributeMaxDynamicSharedMemorySize, (int)sm2);

    vq_k1<<<DD * NS, NT1, sm1>>>(cw_q, codebook, ema, out_onehot, out_cb, out_ema);
    vq_k2<<<DD, 256, sm2>>>(cw_q, codebook, ema, out_embed, out_onehot, out_cb, out_ema);
}